// round 1
// baseline (speedup 1.0000x reference)
#include <cuda_runtime.h>

#define N_ELEMS 33554432
#define N4 (N_ELEMS / 4)   // 8388608 float4 work items

__global__ __launch_bounds__(256) void ssvi_kernel(
    const float4* __restrict__ logm,
    const float4* __restrict__ yATM,
    const float* __restrict__ raw_rho,
    const float* __restrict__ raw_eta,
    const float* __restrict__ raw_gamma,
    float4* __restrict__ out)
{
    int i = blockIdx.x * blockDim.x + threadIdx.x;
    if (i >= N4) return;

    // Broadcast scalars — L2/L1-cached single-element loads, compute per-thread.
    float rho   = tanhf(raw_rho[0]);
    float eta   = __expf(raw_eta[0]);
    float gamma = __expf(raw_gamma[0]);
    float one_m_rho2 = 1.0f - rho * rho;

    float4 lm = logm[i];
    float4 y  = yATM[i];

    float4 o, g1, g2;
    const float4 zero = make_float4(0.f, 0.f, 0.f, 0.f);

    #pragma unroll
    for (int c = 0; c < 4; ++c) {
        float lmv = (&lm.x)[c];
        float yv  = (&y.x)[c];

        // phi = eta / (y^gamma * (1+y)^(1-gamma))
        //     = eta * exp(-(gamma*log(y) + (1-gamma)*log(1+y)))
        float ly  = __logf(yv);
        float l1y = __logf(1.0f + yv);
        float phi = eta * __expf(-(gamma * ly + (1.0f - gamma) * l1y));

        float pl  = phi * lmv;
        float arg = fmaf(pl, pl, fmaf(2.0f * rho, pl, 1.0f));  // pl^2 + 2*rho*pl + 1
        float invS = rsqrtf(arg);
        float S    = arg * invS;
        float half_y = 0.5f * yv;

        (&o.x)[c]  = half_y * (1.0f + rho * pl + S);
        (&g1.x)[c] = half_y * phi * (rho + (pl + rho) * invS);
        float invS3 = invS * invS * invS;
        (&g2.x)[c] = half_y * phi * phi * one_m_rho2 * invS3;
    }

    out[i]          = o;     // output
    out[N4 + i]     = zero;  // grad_ttm1 (zeros; d_out is poisoned)
    out[2 * N4 + i] = g1;    // grad_logm1
    out[3 * N4 + i] = g2;    // grad_logm2
}

extern "C" void kernel_launch(void* const* d_in, const int* in_sizes, int n_in,
                              void* d_out, int out_size)
{
    const float4* logm = (const float4*)d_in[0];
    const float4* yATM = (const float4*)d_in[1];
    const float* raw_rho   = (const float*)d_in[2];
    const float* raw_eta   = (const float*)d_in[3];
    const float* raw_gamma = (const float*)d_in[4];
    float4* out = (float4*)d_out;

    const int threads = 256;
    const int blocks = (N4 + threads - 1) / threads;
    ssvi_kernel<<<blocks, threads>>>(logm, yATM, raw_rho, raw_eta, raw_gamma, out);
}